// round 15
// baseline (speedup 1.0000x reference)
#include <cuda_runtime.h>
#include <cuda_fp16.h>
#include <math.h>
#include <stdint.h>

// Problem constants
#define BDIM   32
#define NTRAJ  512
#define LAT    256
#define HID    1024
#define TSTEPS 10
// The ODE is row-local: tanh(x@W1+b1)@W2 never couples rows. The corrcoef
// block (rows 512..767 per batch) is discarded by the final slice, so we
// only evolve the 512 trajectory rows per batch.
#define MTOT   (BDIM * NTRAJ)       // 16384 rows

// ---------------- scratch ----------------------------------------------------
__device__ __align__(16) float  g_x   [MTOT * LAT];   // committed state (fp32)
__device__ __align__(16) float  g_ksum[MTOT * LAT];   // weighted k accum (fp32)
__device__ __align__(16) __half g_xin [MTOT * LAT];   // next eval input (fp16)
__device__ __align__(16) __half g_h   [MTOT * HID];   // hidden (fp16)
__device__ __align__(16) __half g_W1T [HID * LAT];    // W1^T [n=1024][k=256]
__device__ __align__(16) __half g_W2T [LAT * HID];    // W2^T [n=256][k=1024]

// ---------------- helpers -----------------------------------------------------
__device__ __forceinline__ float tanh_fast(float x) {
    float y;
    asm("tanh.approx.f32 %0, %1;" : "=f"(y) : "f"(x));
    return y;
}

__device__ __forceinline__ void mma_fp16(float* d, const uint32_t* a,
                                         uint32_t b0, uint32_t b1) {
    asm("mma.sync.aligned.m16n8k16.row.col.f32.f16.f16.f32 "
        "{%0,%1,%2,%3},{%4,%5,%6,%7},{%8,%9},{%0,%1,%2,%3};"
        : "+f"(d[0]), "+f"(d[1]), "+f"(d[2]), "+f"(d[3])
        : "r"(a[0]), "r"(a[1]), "r"(a[2]), "r"(a[3]), "r"(b0), "r"(b1));
}

__device__ __forceinline__ void ldsm4(uint32_t* r, uint32_t addr) {
    asm volatile("ldmatrix.sync.aligned.m8n8.x4.shared.b16 {%0,%1,%2,%3}, [%4];"
                 : "=r"(r[0]), "=r"(r[1]), "=r"(r[2]), "=r"(r[3]) : "r"(addr));
}

__device__ __forceinline__ void cp16(uint32_t dst, const void* src) {
    asm volatile("cp.async.cg.shared.global [%0], [%1], 16;"
                 :: "r"(dst), "l"(src));
}
__device__ __forceinline__ void cp_commit() {
    asm volatile("cp.async.commit_group;" ::: "memory");
}
template<int N>
__device__ __forceinline__ void cp_wait() {
    asm volatile("cp.async.wait_group %0;" :: "n"(N) : "memory");
}

__device__ __forceinline__ uint32_t smem_u32(const void* p) {
    uint32_t a;
    asm("{ .reg .u64 t; cvta.to.shared.u64 t, %1; cvt.u32.u64 %0, t; }"
        : "=r"(a) : "l"(p));
    return a;
}

__device__ __forceinline__ uint32_t pack_h2(float lo, float hi) {
    uint32_t p;
    asm("cvt.rn.f16x2.f32 %0, %1, %2;" : "=r"(p) : "f"(hi), "f"(lo));
    return p;
}

// ---------------- setup kernels ----------------------------------------------
__global__ void k_init(const float* __restrict__ fp, float* __restrict__ out) {
    int i = blockIdx.x * blockDim.x + threadIdx.x;
    if (i >= MTOT * LAT) return;
    int c = i % LAT;
    int row = i / LAT;          // = b*NTRAJ + n
    float v = fp[i];
    g_x[i] = v;
    g_xin[i] = __float2half(v);
    out[((size_t)row * TSTEPS + 0) * LAT + c] = v;
}

__global__ void k_w1t(const float* __restrict__ W1) {
    int i = blockIdx.x * blockDim.x + threadIdx.x;
    if (i >= LAT * HID) return;
    int k = i / HID, n = i % HID;
    g_W1T[(size_t)n * LAT + k] = __float2half(W1[i]);
}
__global__ void k_w2t(const float* __restrict__ W2) {
    int i = blockIdx.x * blockDim.x + threadIdx.x;
    if (i >= HID * LAT) return;
    int k = i / LAT, n = i % LAT;
    g_W2T[(size_t)n * HID + k] = __float2half(W2[i]);
}

// ---------------- fp16 GEMM: 256x128 tile, 512 thr, warp 64x32 ---------------
// 16 warps: 4 in m (64 rows each) x 4 in n (32 cols each).
// k-chunk = 64 halfs per stage (128B payload/row, 144B padded rows).
// 3-stage cp.async pipeline, ldmatrix.x4, software-pipelined fragments.
//
// IS_G1: A=g_xin (K=256), B=g_W1T, epilogue tanh(.+b1) -> g_h
// else : A=g_h   (K=1024), B=g_W2T, epilogue RK4 bookkeeping (mode 0/1/2)
#define ROWP      144                  // padded smem row bytes
#define TILE_A    (256 * ROWP)         // 36864 B
#define TILE_Bb   (128 * ROWP)         // 18432 B
#define STG_BYTES (TILE_A + TILE_Bb)   // 55296 B
#define SMEM_TOT  (3 * STG_BYTES)      // 165888 B

template<int KDIM, bool IS_G1>
__global__ __launch_bounds__(512, 1)
void k_mm(const float* __restrict__ b1v, const float* __restrict__ ts, int step,
          int mode, float cnext, float* __restrict__ out) {
    constexpr int NIT  = KDIM / 64;
    constexpr int ROWB = KDIM * 2;

    extern __shared__ __align__(16) char sm[];
    const uint32_t smB = smem_u32(sm);

    const int m0 = blockIdx.y * 256;
    const int n0 = blockIdx.x * 128;
    const int tid  = threadIdx.x;
    const int lane = tid & 31;
    const int warp = tid >> 5;
    const int wm = warp & 3;            // m quarter (64 rows)
    const int wn = warp >> 2;           // n quarter (32 cols)
    const int r  = lane >> 2;
    const int cq = lane & 3;

    // ldmatrix per-lane address parts
    const int sub = lane >> 3;
    const int rowPart = ((sub & 1) * 8 + (lane & 7));
    const int colPart = (sub >> 1) * 16;

    // cp.async mapping: A 4 cp16/thread (256 rows), B 2 cp16/thread (128 rows)
    const int cRow0 = tid >> 3;         // 0..63
    const int cSeg  = tid & 7;

    const char* Ag = (const char*)(IS_G1 ? g_xin : g_h)
                   + (size_t)m0 * ROWB + cSeg * 16;
    const char* Bg = (const char*)(IS_G1 ? g_W1T : g_W2T)
                   + (size_t)n0 * ROWB + cSeg * 16;

    auto copyStage = [&](int it, int s) {
        uint32_t so = smB + (uint32_t)s * STG_BYTES;
        #pragma unroll
        for (int o = 0; o < 4; o++) {
            int row = cRow0 + o * 64;
            cp16(so + row * ROWP + cSeg * 16,
                 Ag + (size_t)row * ROWB + it * 128);
        }
        #pragma unroll
        for (int o = 0; o < 2; o++) {
            int row = cRow0 + o * 64;
            cp16(so + TILE_A + row * ROWP + cSeg * 16,
                 Bg + (size_t)row * ROWB + it * 128);
        }
        cp_commit();
    };

    float acc[4][4][4] = {};

    copyStage(0, 0);
    copyStage(1, 1);

    #pragma unroll 1
    for (int it = 0; it < NIT; it++) {
        if (it + 1 < NIT) cp_wait<1>(); else cp_wait<0>();
        __syncthreads();
        if (it + 2 < NIT) copyStage(it + 2, (it + 2) % 3);

        const uint32_t aBase = smB + (uint32_t)(it % 3) * STG_BYTES
                             + (wm * 64 + rowPart) * ROWP + colPart;
        const uint32_t bBase = smB + (uint32_t)(it % 3) * STG_BYTES + TILE_A
                             + (wn * 32 + rowPart) * ROWP + colPart;

        uint32_t bq[2][8], af[2][4];
        ldsm4(bq[0],     bBase);
        ldsm4(bq[0] + 4, bBase + 16 * ROWP);
        ldsm4(af[0],     aBase);

        #pragma unroll
        for (int kq = 0; kq < 4; kq++) {
            const int kb = kq & 1;
            #pragma unroll
            for (int mt = 0; mt < 4; mt++) {
                if (mt < 3) {
                    ldsm4(af[(mt + 1) & 1], aBase + (mt + 1) * (16 * ROWP) + kq * 32);
                } else if (kq < 3) {
                    ldsm4(bq[kb ^ 1],     bBase + (kq + 1) * 32);
                    ldsm4(bq[kb ^ 1] + 4, bBase + 16 * ROWP + (kq + 1) * 32);
                    ldsm4(af[0],          aBase + (kq + 1) * 32);
                }
                const uint32_t* B = bq[kb];
                const uint32_t* A = af[mt & 1];
                mma_fp16(acc[mt][0], A, B[0], B[2]);
                mma_fp16(acc[mt][1], A, B[1], B[3]);
                mma_fp16(acc[mt][2], A, B[4], B[6]);
                mma_fp16(acc[mt][3], A, B[5], B[7]);
            }
        }
    }

    // ---------------- epilogue ----------------
    if (IS_G1) {
        #pragma unroll
        for (int mt = 0; mt < 4; mt++) {
            int row0 = m0 + wm * 64 + mt * 16 + r;
            #pragma unroll
            for (int nt = 0; nt < 4; nt++) {
                int col = n0 + wn * 32 + nt * 8 + 2 * cq;
                float bx = __ldg(b1v + col), by = __ldg(b1v + col + 1);
                float t0 = tanh_fast(acc[mt][nt][0] + bx);
                float t1 = tanh_fast(acc[mt][nt][1] + by);
                float t2 = tanh_fast(acc[mt][nt][2] + bx);
                float t3 = tanh_fast(acc[mt][nt][3] + by);
                *(uint32_t*)((char*)g_h + ((size_t)row0 * HID + col) * 2)
                    = pack_h2(t0, t1);
                *(uint32_t*)((char*)g_h + ((size_t)(row0 + 8) * HID + col) * 2)
                    = pack_h2(t2, t3);
            }
        }
    } else {
        const float dt = ts[step + 1] - ts[step];
        const float cn = cnext * dt;
        const float s6 = dt * (1.0f / 6.0f);

        #pragma unroll
        for (int mt = 0; mt < 4; mt++) {
            #pragma unroll
            for (int h = 0; h < 2; h++) {
                int row = m0 + wm * 64 + mt * 16 + r + 8 * h;   // = b*NTRAJ + n
                #pragma unroll
                for (int nt = 0; nt < 4; nt++) {
                    int col = n0 + wn * 32 + nt * 8 + 2 * cq;
                    float v0 = acc[mt][nt][2 * h + 0];
                    float v1 = acc[mt][nt][2 * h + 1];
                    size_t idx = (size_t)row * LAT + col;
                    if (mode == 0) {
                        g_ksum[idx] = v0;  g_ksum[idx + 1] = v1;
                        float xi0 = fmaf(cn, v0, g_x[idx]);
                        float xi1 = fmaf(cn, v1, g_x[idx + 1]);
                        *(uint32_t*)((char*)g_xin + idx * 2) = pack_h2(xi0, xi1);
                    } else if (mode == 1) {
                        g_ksum[idx]     += 2.f * v0;
                        g_ksum[idx + 1] += 2.f * v1;
                        float xi0 = fmaf(cn, v0, g_x[idx]);
                        float xi1 = fmaf(cn, v1, g_x[idx + 1]);
                        *(uint32_t*)((char*)g_xin + idx * 2) = pack_h2(xi0, xi1);
                    } else {
                        float x0 = g_x[idx] + s6 * (g_ksum[idx] + v0);
                        float x1 = g_x[idx + 1] + s6 * (g_ksum[idx + 1] + v1);
                        g_x[idx] = x0;   g_x[idx + 1] = x1;
                        *(uint32_t*)((char*)g_xin + idx * 2) = pack_h2(x0, x1);
                        size_t o = ((size_t)row * TSTEPS + (step + 1)) * LAT + col;
                        out[o] = x0; out[o + 1] = x1;
                    }
                }
            }
        }
    }
}

// ---------------- launch ------------------------------------------------------
extern "C" void kernel_launch(void* const* d_in, const int* in_sizes, int n_in,
                              void* d_out, int out_size) {
    const float* fp = (const float*)d_in[0];
    const float* ts = (const float*)d_in[1];
    const float* W1 = (const float*)d_in[2];
    const float* b1 = (const float*)d_in[3];
    const float* W2 = (const float*)d_in[4];
    float* out = (float*)d_out;

    static int attr_done = 0;
    if (!attr_done) {
        cudaFuncSetAttribute(k_mm<LAT, true>,
                             cudaFuncAttributeMaxDynamicSharedMemorySize, SMEM_TOT);
        cudaFuncSetAttribute(k_mm<HID, false>,
                             cudaFuncAttributeMaxDynamicSharedMemorySize, SMEM_TOT);
        attr_done = 1;
    }

    k_init<<<(MTOT * LAT + 255) / 256, 256>>>(fp, out);
    k_w1t<<<(LAT * HID + 255) / 256, 256>>>(W1);
    k_w2t<<<(HID * LAT + 255) / 256, 256>>>(W2);

    dim3 g1(HID / 128, MTOT / 256);   // (8, 64) = 512 blocks
    dim3 g2(LAT / 128, MTOT / 256);   // (2, 64) = 128 blocks

    for (int s = 0; s < TSTEPS - 1; s++) {
        // eval 1 -> k1: ksum = k1,  xin = x + 0.5*dt*k1
        k_mm<LAT,  true ><<<g1, 512, SMEM_TOT>>>(b1, ts, s, 0, 0.0f, nullptr);
        k_mm<HID,  false><<<g2, 512, SMEM_TOT>>>(nullptr, ts, s, 0, 0.5f, out);
        // eval 2 -> k2: ksum += 2*k2, xin = x + 0.5*dt*k2
        k_mm<LAT,  true ><<<g1, 512, SMEM_TOT>>>(b1, ts, s, 0, 0.0f, nullptr);
        k_mm<HID,  false><<<g2, 512, SMEM_TOT>>>(nullptr, ts, s, 1, 0.5f, out);
        // eval 3 -> k3: ksum += 2*k3, xin = x + dt*k3
        k_mm<LAT,  true ><<<g1, 512, SMEM_TOT>>>(b1, ts, s, 0, 0.0f, nullptr);
        k_mm<HID,  false><<<g2, 512, SMEM_TOT>>>(nullptr, ts, s, 1, 1.0f, out);
        // eval 4 -> k4: x += dt/6*(ksum + k4); write slice; xin = x_new
        k_mm<LAT,  true ><<<g1, 512, SMEM_TOT>>>(b1, ts, s, 0, 0.0f, nullptr);
        k_mm<HID,  false><<<g2, 512, SMEM_TOT>>>(nullptr, ts, s, 2, 0.0f, out);
    }
}

// round 16
// speedup vs baseline: 1.0627x; 1.0627x over previous
#include <cuda_runtime.h>
#include <cuda_fp16.h>
#include <math.h>
#include <stdint.h>

// Problem constants
#define BDIM   32
#define NTRAJ  512
#define LAT    256
#define HID    1024
#define TSTEPS 10
// The ODE is row-local: tanh(x@W1+b1)@W2 never couples rows. The corrcoef
// block (rows 512..767 per batch) is discarded by the final slice, so we
// only evolve the 512 trajectory rows per batch.
#define MTOT   (BDIM * NTRAJ)       // 16384 rows

// ---------------- scratch ----------------------------------------------------
__device__ __align__(16) float  g_x   [MTOT * LAT];   // committed state (fp32)
__device__ __align__(16) float  g_ksum[MTOT * LAT];   // weighted k accum (fp32)
__device__ __align__(16) __half g_xin [MTOT * LAT];   // next eval input (fp16)
__device__ __align__(16) __half g_h   [MTOT * HID];   // hidden (fp16)
__device__ __align__(16) __half g_W1T [HID * LAT];    // W1^T [n=1024][k=256]
__device__ __align__(16) __half g_W2T [LAT * HID];    // W2^T [n=256][k=1024]

// ---------------- helpers -----------------------------------------------------
__device__ __forceinline__ float tanh_fast(float x) {
    float y;
    asm("tanh.approx.f32 %0, %1;" : "=f"(y) : "f"(x));
    return y;
}

__device__ __forceinline__ void mma_fp16(float* d, const uint32_t* a,
                                         uint32_t b0, uint32_t b1) {
    asm("mma.sync.aligned.m16n8k16.row.col.f32.f16.f16.f32 "
        "{%0,%1,%2,%3},{%4,%5,%6,%7},{%8,%9},{%0,%1,%2,%3};"
        : "+f"(d[0]), "+f"(d[1]), "+f"(d[2]), "+f"(d[3])
        : "r"(a[0]), "r"(a[1]), "r"(a[2]), "r"(a[3]), "r"(b0), "r"(b1));
}

__device__ __forceinline__ void ldsm4(uint32_t* r, uint32_t addr) {
    asm volatile("ldmatrix.sync.aligned.m8n8.x4.shared.b16 {%0,%1,%2,%3}, [%4];"
                 : "=r"(r[0]), "=r"(r[1]), "=r"(r[2]), "=r"(r[3]) : "r"(addr));
}

__device__ __forceinline__ void cp16(uint32_t dst, const void* src) {
    asm volatile("cp.async.cg.shared.global [%0], [%1], 16;"
                 :: "r"(dst), "l"(src));
}
__device__ __forceinline__ void cp_commit() {
    asm volatile("cp.async.commit_group;" ::: "memory");
}
template<int N>
__device__ __forceinline__ void cp_wait() {
    asm volatile("cp.async.wait_group %0;" :: "n"(N) : "memory");
}

__device__ __forceinline__ uint32_t smem_u32(const void* p) {
    uint32_t a;
    asm("{ .reg .u64 t; cvta.to.shared.u64 t, %1; cvt.u32.u64 %0, t; }"
        : "=r"(a) : "l"(p));
    return a;
}

__device__ __forceinline__ uint32_t pack_h2(float lo, float hi) {
    uint32_t p;
    asm("cvt.rn.f16x2.f32 %0, %1, %2;" : "=r"(p) : "f"(hi), "f"(lo));
    return p;
}

// ---------------- setup kernels ----------------------------------------------
__global__ void k_init(const float* __restrict__ fp, float* __restrict__ out) {
    int i = blockIdx.x * blockDim.x + threadIdx.x;
    if (i >= MTOT * LAT) return;
    int c = i % LAT;
    int row = i / LAT;          // = b*NTRAJ + n
    float v = fp[i];
    g_x[i] = v;
    g_xin[i] = __float2half(v);
    out[((size_t)row * TSTEPS + 0) * LAT + c] = v;
}

__global__ void k_w1t(const float* __restrict__ W1) {
    int i = blockIdx.x * blockDim.x + threadIdx.x;
    if (i >= LAT * HID) return;
    int k = i / HID, n = i % HID;
    g_W1T[(size_t)n * LAT + k] = __float2half(W1[i]);
}
__global__ void k_w2t(const float* __restrict__ W2) {
    int i = blockIdx.x * blockDim.x + threadIdx.x;
    if (i >= HID * LAT) return;
    int k = i / LAT, n = i % LAT;
    g_W2T[(size_t)n * HID + k] = __float2half(W2[i]);
}

// ---------------- fp16 GEMM: 128x128 tile, 256 thr, warp 64x32 ---------------
// k-chunk = 64 halfs per stage (128B payload/row, 144B padded rows).
// 3-stage cp.async pipeline, ldmatrix.x4, deep fragment pipeline:
// A fragments triple-buffered (prefetch distance 2 steps > LDS latency),
// B fragments double-buffered, prefetched 3 steps ahead.
//
// IS_G1: A=g_xin (K=256), B=g_W1T, epilogue tanh(.+b1) -> g_h
// else : A=g_h   (K=1024), B=g_W2T, epilogue RK4 bookkeeping (mode 0/1/2)
#define ROWP      144                  // padded smem row bytes
#define TILE_B    (128 * ROWP)         // one operand tile (18432 B)
#define STG_BYTES (2 * TILE_B)         // A + B per stage (36864 B)
#define SMEM_TOT  (3 * STG_BYTES)      // 110592 B

template<int KDIM, bool IS_G1>
__global__ __launch_bounds__(256, 2)
void k_mm(const float* __restrict__ b1v, const float* __restrict__ ts, int step,
          int mode, float cnext, float* __restrict__ out) {
    constexpr int NIT  = KDIM / 64;
    constexpr int ROWB = KDIM * 2;

    extern __shared__ __align__(16) char sm[];
    const uint32_t smB = smem_u32(sm);

    const int m0 = blockIdx.y * 128;
    const int n0 = blockIdx.x * 128;
    const int tid  = threadIdx.x;
    const int lane = tid & 31;
    const int warp = tid >> 5;
    const int wm = warp & 1;            // m half (64 rows)
    const int wn = warp >> 1;           // n quarter (32 cols)
    const int r  = lane >> 2;
    const int cq = lane & 3;

    // ldmatrix per-lane address parts
    const int sub = lane >> 3;
    const int rowPart = ((sub & 1) * 8 + (lane & 7));
    const int colPart = (sub >> 1) * 16;

    // cp.async mapping: 4 A + 4 B cp16 per thread per stage
    const int cRow0 = tid >> 3;
    const int cSeg  = tid & 7;

    const char* Ag = (const char*)(IS_G1 ? g_xin : g_h)
                   + (size_t)m0 * ROWB + cSeg * 16;
    const char* Bg = (const char*)(IS_G1 ? g_W1T : g_W2T)
                   + (size_t)n0 * ROWB + cSeg * 16;

    auto copyStage = [&](int it, int s) {
        uint32_t so = smB + (uint32_t)s * STG_BYTES;
        #pragma unroll
        for (int o = 0; o < 4; o++) {
            int row = cRow0 + o * 32;
            cp16(so + row * ROWP + cSeg * 16,
                 Ag + (size_t)row * ROWB + it * 128);
        }
        #pragma unroll
        for (int o = 0; o < 4; o++) {
            int row = cRow0 + o * 32;
            cp16(so + TILE_B + row * ROWP + cSeg * 16,
                 Bg + (size_t)row * ROWB + it * 128);
        }
        cp_commit();
    };

    float acc[4][4][4] = {};

    copyStage(0, 0);
    copyStage(1, 1);

    #pragma unroll 1
    for (int it = 0; it < NIT; it++) {
        if (it + 1 < NIT) cp_wait<1>(); else cp_wait<0>();
        __syncthreads();
        if (it + 2 < NIT) copyStage(it + 2, (it + 2) % 3);

        const uint32_t aBase = smB + (uint32_t)(it % 3) * STG_BYTES
                             + (wm * 64 + rowPart) * ROWP + colPart;
        const uint32_t bBase = smB + (uint32_t)(it % 3) * STG_BYTES + TILE_B
                             + (wn * 32 + rowPart) * ROWP + colPart;

        // deep fragment pipeline over 16 steps: s = kq*4 + mt
        uint32_t bq[2][8], af[3][4];
        ldsm4(bq[0],     bBase);
        ldsm4(bq[0] + 4, bBase + 16 * ROWP);
        ldsm4(af[0],     aBase);                  // s=0 (kq0,mt0)
        ldsm4(af[1],     aBase + 16 * ROWP);      // s=1 (kq0,mt1)

        #pragma unroll
        for (int s = 0; s < 16; s++) {
            const int kq = s >> 2;
            const int mt = s & 3;
            // A fragment for step s+2 (distance 2 > LDS latency)
            if (s + 2 < 16) {
                const int s2 = s + 2;
                ldsm4(af[s2 % 3],
                      aBase + (s2 & 3) * (16 * ROWP) + (s2 >> 2) * 32);
            }
            // B fragments for kq+1, issued at mt==1 (distance 3 steps)
            if (mt == 1 && kq < 3) {
                ldsm4(bq[(kq + 1) & 1],     bBase + (kq + 1) * 32);
                ldsm4(bq[(kq + 1) & 1] + 4, bBase + 16 * ROWP + (kq + 1) * 32);
            }
            const uint32_t* B = bq[kq & 1];
            const uint32_t* A = af[s % 3];
            mma_fp16(acc[mt][0], A, B[0], B[2]);
            mma_fp16(acc[mt][1], A, B[1], B[3]);
            mma_fp16(acc[mt][2], A, B[4], B[6]);
            mma_fp16(acc[mt][3], A, B[5], B[7]);
        }
    }

    // ---------------- epilogue ----------------
    if (IS_G1) {
        #pragma unroll
        for (int mt = 0; mt < 4; mt++) {
            int row0 = m0 + wm * 64 + mt * 16 + r;
            #pragma unroll
            for (int nt = 0; nt < 4; nt++) {
                int col = n0 + wn * 32 + nt * 8 + 2 * cq;
                float bx = __ldg(b1v + col), by = __ldg(b1v + col + 1);
                float t0 = tanh_fast(acc[mt][nt][0] + bx);
                float t1 = tanh_fast(acc[mt][nt][1] + by);
                float t2 = tanh_fast(acc[mt][nt][2] + bx);
                float t3 = tanh_fast(acc[mt][nt][3] + by);
                *(uint32_t*)((char*)g_h + ((size_t)row0 * HID + col) * 2)
                    = pack_h2(t0, t1);
                *(uint32_t*)((char*)g_h + ((size_t)(row0 + 8) * HID + col) * 2)
                    = pack_h2(t2, t3);
            }
        }
    } else {
        const float dt = ts[step + 1] - ts[step];
        const float cn = cnext * dt;
        const float s6 = dt * (1.0f / 6.0f);

        #pragma unroll
        for (int mt = 0; mt < 4; mt++) {
            #pragma unroll
            for (int h = 0; h < 2; h++) {
                int row = m0 + wm * 64 + mt * 16 + r + 8 * h;   // = b*NTRAJ + n
                #pragma unroll
                for (int nt = 0; nt < 4; nt++) {
                    int col = n0 + wn * 32 + nt * 8 + 2 * cq;
                    float v0 = acc[mt][nt][2 * h + 0];
                    float v1 = acc[mt][nt][2 * h + 1];
                    size_t idx = (size_t)row * LAT + col;
                    if (mode == 0) {
                        g_ksum[idx] = v0;  g_ksum[idx + 1] = v1;
                        float xi0 = fmaf(cn, v0, g_x[idx]);
                        float xi1 = fmaf(cn, v1, g_x[idx + 1]);
                        *(uint32_t*)((char*)g_xin + idx * 2) = pack_h2(xi0, xi1);
                    } else if (mode == 1) {
                        g_ksum[idx]     += 2.f * v0;
                        g_ksum[idx + 1] += 2.f * v1;
                        float xi0 = fmaf(cn, v0, g_x[idx]);
                        float xi1 = fmaf(cn, v1, g_x[idx + 1]);
                        *(uint32_t*)((char*)g_xin + idx * 2) = pack_h2(xi0, xi1);
                    } else {
                        float x0 = g_x[idx] + s6 * (g_ksum[idx] + v0);
                        float x1 = g_x[idx + 1] + s6 * (g_ksum[idx + 1] + v1);
                        g_x[idx] = x0;   g_x[idx + 1] = x1;
                        *(uint32_t*)((char*)g_xin + idx * 2) = pack_h2(x0, x1);
                        size_t o = ((size_t)row * TSTEPS + (step + 1)) * LAT + col;
                        out[o] = x0; out[o + 1] = x1;
                    }
                }
            }
        }
    }
}

// ---------------- launch ------------------------------------------------------
extern "C" void kernel_launch(void* const* d_in, const int* in_sizes, int n_in,
                              void* d_out, int out_size) {
    const float* fp = (const float*)d_in[0];
    const float* ts = (const float*)d_in[1];
    const float* W1 = (const float*)d_in[2];
    const float* b1 = (const float*)d_in[3];
    const float* W2 = (const float*)d_in[4];
    float* out = (float*)d_out;

    static int attr_done = 0;
    if (!attr_done) {
        cudaFuncSetAttribute(k_mm<LAT, true>,
                             cudaFuncAttributeMaxDynamicSharedMemorySize, SMEM_TOT);
        cudaFuncSetAttribute(k_mm<HID, false>,
                             cudaFuncAttributeMaxDynamicSharedMemorySize, SMEM_TOT);
        attr_done = 1;
    }

    k_init<<<(MTOT * LAT + 255) / 256, 256>>>(fp, out);
    k_w1t<<<(LAT * HID + 255) / 256, 256>>>(W1);
    k_w2t<<<(HID * LAT + 255) / 256, 256>>>(W2);

    dim3 g1(HID / 128, MTOT / 128);   // (8, 128) = 1024 blocks
    dim3 g2(LAT / 128, MTOT / 128);   // (2, 128) = 256 blocks

    for (int s = 0; s < TSTEPS - 1; s++) {
        // eval 1 -> k1: ksum = k1,  xin = x + 0.5*dt*k1
        k_mm<LAT,  true ><<<g1, 256, SMEM_TOT>>>(b1, ts, s, 0, 0.0f, nullptr);
        k_mm<HID,  false><<<g2, 256, SMEM_TOT>>>(nullptr, ts, s, 0, 0.5f, out);
        // eval 2 -> k2: ksum += 2*k2, xin = x + 0.5*dt*k2
        k_mm<LAT,  true ><<<g1, 256, SMEM_TOT>>>(b1, ts, s, 0, 0.0f, nullptr);
        k_mm<HID,  false><<<g2, 256, SMEM_TOT>>>(nullptr, ts, s, 1, 0.5f, out);
        // eval 3 -> k3: ksum += 2*k3, xin = x + dt*k3
        k_mm<LAT,  true ><<<g1, 256, SMEM_TOT>>>(b1, ts, s, 0, 0.0f, nullptr);
        k_mm<HID,  false><<<g2, 256, SMEM_TOT>>>(nullptr, ts, s, 1, 1.0f, out);
        // eval 4 -> k4: x += dt/6*(ksum + k4); write slice; xin = x_new
        k_mm<LAT,  true ><<<g1, 256, SMEM_TOT>>>(b1, ts, s, 0, 0.0f, nullptr);
        k_mm<HID,  false><<<g2, 256, SMEM_TOT>>>(nullptr, ts, s, 2, 0.0f, out);
    }
}

// round 17
// speedup vs baseline: 1.0714x; 1.0082x over previous
#include <cuda_runtime.h>
#include <cuda_fp16.h>
#include <math.h>
#include <stdint.h>

// Problem constants
#define BDIM   32
#define NTRAJ  512
#define LAT    256
#define HID    1024
#define TSTEPS 10
// The ODE is row-local: tanh(x@W1+b1)@W2 never couples rows. The corrcoef
// block (rows 512..767 per batch) is discarded by the final slice, so we
// only evolve the 512 trajectory rows per batch.
#define MTOT   (BDIM * NTRAJ)       // 16384 rows

// ---------------- scratch ----------------------------------------------------
__device__ __align__(16) float  g_x   [MTOT * LAT];   // committed state (fp32)
__device__ __align__(16) float  g_ksum[MTOT * LAT];   // weighted k accum (fp32)
__device__ __align__(16) __half g_xin [MTOT * LAT];   // next eval input (fp16)
__device__ __align__(16) __half g_h   [MTOT * HID];   // hidden (fp16)
__device__ __align__(16) __half g_W1T [HID * LAT];    // W1^T [n=1024][k=256]
__device__ __align__(16) __half g_W2T [LAT * HID];    // W2^T [n=256][k=1024]

// ---------------- helpers -----------------------------------------------------
__device__ __forceinline__ float tanh_fast(float x) {
    float y;
    asm("tanh.approx.f32 %0, %1;" : "=f"(y) : "f"(x));
    return y;
}

// fp32-accumulator MMA
__device__ __forceinline__ void mma_fp16(float* d, const uint32_t* a,
                                         uint32_t b0, uint32_t b1) {
    asm("mma.sync.aligned.m16n8k16.row.col.f32.f16.f16.f32 "
        "{%0,%1,%2,%3},{%4,%5,%6,%7},{%8,%9},{%0,%1,%2,%3};"
        : "+f"(d[0]), "+f"(d[1]), "+f"(d[2]), "+f"(d[3])
        : "r"(a[0]), "r"(a[1]), "r"(a[2]), "r"(a[3]), "r"(b0), "r"(b1));
}

// fp16-accumulator MMA: d0=(c0,c1) packed, d1=(c2,c3) packed
__device__ __forceinline__ void mma_fp16h(uint32_t* d, const uint32_t* a,
                                          uint32_t b0, uint32_t b1) {
    asm("mma.sync.aligned.m16n8k16.row.col.f16.f16.f16.f16 "
        "{%0,%1},{%2,%3,%4,%5},{%6,%7},{%0,%1};"
        : "+r"(d[0]), "+r"(d[1])
        : "r"(a[0]), "r"(a[1]), "r"(a[2]), "r"(a[3]), "r"(b0), "r"(b1));
}

__device__ __forceinline__ void ldsm4(uint32_t* r, uint32_t addr) {
    asm volatile("ldmatrix.sync.aligned.m8n8.x4.shared.b16 {%0,%1,%2,%3}, [%4];"
                 : "=r"(r[0]), "=r"(r[1]), "=r"(r[2]), "=r"(r[3]) : "r"(addr));
}

__device__ __forceinline__ void cp16(uint32_t dst, const void* src) {
    asm volatile("cp.async.cg.shared.global [%0], [%1], 16;"
                 :: "r"(dst), "l"(src));
}
__device__ __forceinline__ void cp_commit() {
    asm volatile("cp.async.commit_group;" ::: "memory");
}
template<int N>
__device__ __forceinline__ void cp_wait() {
    asm volatile("cp.async.wait_group %0;" :: "n"(N) : "memory");
}

__device__ __forceinline__ uint32_t smem_u32(const void* p) {
    uint32_t a;
    asm("{ .reg .u64 t; cvta.to.shared.u64 t, %1; cvt.u32.u64 %0, t; }"
        : "=r"(a) : "l"(p));
    return a;
}

__device__ __forceinline__ uint32_t pack_h2(float lo, float hi) {
    uint32_t p;
    asm("cvt.rn.f16x2.f32 %0, %1, %2;" : "=r"(p) : "f"(hi), "f"(lo));
    return p;
}

// ---------------- setup kernels ----------------------------------------------
__global__ void k_init(const float* __restrict__ fp, float* __restrict__ out) {
    int i = blockIdx.x * blockDim.x + threadIdx.x;
    if (i >= MTOT * LAT) return;
    int c = i % LAT;
    int row = i / LAT;          // = b*NTRAJ + n
    float v = fp[i];
    g_x[i] = v;
    g_xin[i] = __float2half(v);
    out[((size_t)row * TSTEPS + 0) * LAT + c] = v;
}

__global__ void k_w1t(const float* __restrict__ W1) {
    int i = blockIdx.x * blockDim.x + threadIdx.x;
    if (i >= LAT * HID) return;
    int k = i / HID, n = i % HID;
    g_W1T[(size_t)n * LAT + k] = __float2half(W1[i]);
}
__global__ void k_w2t(const float* __restrict__ W2) {
    int i = blockIdx.x * blockDim.x + threadIdx.x;
    if (i >= HID * LAT) return;
    int k = i / LAT, n = i % LAT;
    g_W2T[(size_t)n * HID + k] = __float2half(W2[i]);
}

// ================= G1: fp16-acc GEMM, 128x128 tile, occ 3 ====================
// H = tanh(xin @ W1 + b1) -> g_h.  K=256, k-chunk 32, 3-stage cp.async.
// acc in fp16 (32 regs) -> ~78 regs -> 3 blocks/SM (24 warps).
#define ROWP1 80
#define TILE1 (128 * ROWP1)     // 10240
#define STG1  (2 * TILE1)       // 20480
#define SM1   (3 * STG1)        // 61440

__global__ __launch_bounds__(256, 3)
void k_g1(const float* __restrict__ b1v) {
    constexpr int NIT  = LAT / 32;   // 8
    constexpr int ROWB = LAT * 2;    // 512

    extern __shared__ __align__(16) char sm[];
    const uint32_t smB = smem_u32(sm);

    const int m0 = blockIdx.y * 128;
    const int n0 = blockIdx.x * 128;
    const int tid  = threadIdx.x;
    const int lane = tid & 31;
    const int warp = tid >> 5;
    const int wm = warp & 1;
    const int wn = warp >> 1;
    const int r  = lane >> 2;
    const int cq = lane & 3;

    const int sub = lane >> 3;
    const int rowPart = ((sub & 1) * 8 + (lane & 7));
    const int colPart = (sub >> 1) * 16;

    const int cRow = tid >> 2;      // 0..63 (+64)
    const int cSeg = tid & 3;

    const char* Ag = (const char*)g_xin + (size_t)(m0 + cRow) * ROWB + cSeg * 16;
    const char* Bg = (const char*)g_W1T + (size_t)(n0 + cRow) * ROWB + cSeg * 16;

    auto copyStage = [&](int it, int s) {
        uint32_t so = smB + (uint32_t)s * STG1;
        #pragma unroll
        for (int l = 0; l < 2; l++)
            cp16(so + (cRow + l * 64) * ROWP1 + cSeg * 16,
                 Ag + (size_t)(l * 64) * ROWB + it * 64);
        #pragma unroll
        for (int l = 0; l < 2; l++)
            cp16(so + TILE1 + (cRow + l * 64) * ROWP1 + cSeg * 16,
                 Bg + (size_t)(l * 64) * ROWB + it * 64);
        cp_commit();
    };

    uint32_t acc[4][4][2] = {};

    copyStage(0, 0);
    copyStage(1, 1);

    #pragma unroll 1
    for (int it = 0; it < NIT; it++) {
        if (it + 1 < NIT) cp_wait<1>(); else cp_wait<0>();
        __syncthreads();
        if (it + 2 < NIT) copyStage(it + 2, (it + 2) % 3);

        const uint32_t aB = smB + (uint32_t)(it % 3) * STG1;
        const uint32_t bB = aB + TILE1;

        #pragma unroll
        for (int ks = 0; ks < 2; ks++) {
            uint32_t bq0[4], bq1[4];
            ldsm4(bq0, bB + (wn * 32 + rowPart) * ROWP1 + ks * 32 + colPart);
            ldsm4(bq1, bB + (wn * 32 + 16 + rowPart) * ROWP1 + ks * 32 + colPart);
            #pragma unroll
            for (int mt = 0; mt < 4; mt++) {
                uint32_t af[4];
                ldsm4(af, aB + (wm * 64 + mt * 16 + rowPart) * ROWP1
                          + ks * 32 + colPart);
                mma_fp16h(acc[mt][0], af, bq0[0], bq0[2]);
                mma_fp16h(acc[mt][1], af, bq0[1], bq0[3]);
                mma_fp16h(acc[mt][2], af, bq1[0], bq1[2]);
                mma_fp16h(acc[mt][3], af, bq1[1], bq1[3]);
            }
        }
    }

    // epilogue: unpack fp16 acc, add bias, tanh, store bf... fp16 g_h
    #pragma unroll
    for (int mt = 0; mt < 4; mt++) {
        int row0 = m0 + wm * 64 + mt * 16 + r;
        #pragma unroll
        for (int nt = 0; nt < 4; nt++) {
            int col = n0 + wn * 32 + nt * 8 + 2 * cq;
            float bx = __ldg(b1v + col), by = __ldg(b1v + col + 1);
            float2 f01 = __half22float2(*(__half2*)&acc[mt][nt][0]);
            float2 f23 = __half22float2(*(__half2*)&acc[mt][nt][1]);
            float t0 = tanh_fast(f01.x + bx);
            float t1 = tanh_fast(f01.y + by);
            float t2 = tanh_fast(f23.x + bx);
            float t3 = tanh_fast(f23.y + by);
            *(uint32_t*)((char*)g_h + ((size_t)row0 * HID + col) * 2)
                = pack_h2(t0, t1);
            *(uint32_t*)((char*)g_h + ((size_t)(row0 + 8) * HID + col) * 2)
                = pack_h2(t2, t3);
        }
    }
}

// ================= G2: fp32-acc GEMM (R10 config), occ 2 =====================
// Kv = h @ W2, fused RK4 epilogue. K=1024, k-chunk 64, 3-stage cp.async.
#define ROWP2 144
#define TILE2 (128 * ROWP2)     // 18432
#define STG2  (2 * TILE2)       // 36864
#define SM2   (3 * STG2)        // 110592

__global__ __launch_bounds__(256, 2)
void k_g2(const float* __restrict__ ts, int step, int mode, float cnext,
          float* __restrict__ out) {
    constexpr int NIT  = HID / 64;   // 16
    constexpr int ROWB = HID * 2;    // 2048

    extern __shared__ __align__(16) char sm[];
    const uint32_t smB = smem_u32(sm);

    const int m0 = blockIdx.y * 128;
    const int n0 = blockIdx.x * 128;
    const int tid  = threadIdx.x;
    const int lane = tid & 31;
    const int warp = tid >> 5;
    const int wm = warp & 1;
    const int wn = warp >> 1;
    const int r  = lane >> 2;
    const int cq = lane & 3;

    const int sub = lane >> 3;
    const int rowPart = ((sub & 1) * 8 + (lane & 7));
    const int colPart = (sub >> 1) * 16;

    const int cRow0 = tid >> 3;
    const int cSeg  = tid & 7;

    const char* Ag = (const char*)g_h   + (size_t)m0 * ROWB + cSeg * 16;
    const char* Bg = (const char*)g_W2T + (size_t)n0 * ROWB + cSeg * 16;

    auto copyStage = [&](int it, int s) {
        uint32_t so = smB + (uint32_t)s * STG2;
        #pragma unroll
        for (int o = 0; o < 4; o++) {
            int row = cRow0 + o * 32;
            cp16(so + row * ROWP2 + cSeg * 16,
                 Ag + (size_t)row * ROWB + it * 128);
        }
        #pragma unroll
        for (int o = 0; o < 4; o++) {
            int row = cRow0 + o * 32;
            cp16(so + TILE2 + row * ROWP2 + cSeg * 16,
                 Bg + (size_t)row * ROWB + it * 128);
        }
        cp_commit();
    };

    float acc[4][4][4] = {};

    copyStage(0, 0);
    copyStage(1, 1);

    #pragma unroll 1
    for (int it = 0; it < NIT; it++) {
        if (it + 1 < NIT) cp_wait<1>(); else cp_wait<0>();
        __syncthreads();
        if (it + 2 < NIT) copyStage(it + 2, (it + 2) % 3);

        const uint32_t aBase = smB + (uint32_t)(it % 3) * STG2
                             + (wm * 64 + rowPart) * ROWP2 + colPart;
        const uint32_t bBase = smB + (uint32_t)(it % 3) * STG2 + TILE2
                             + (wn * 32 + rowPart) * ROWP2 + colPart;

        uint32_t bq[2][8], af[2][4];
        ldsm4(bq[0],     bBase);
        ldsm4(bq[0] + 4, bBase + 16 * ROWP2);
        ldsm4(af[0],     aBase);

        #pragma unroll
        for (int kq = 0; kq < 4; kq++) {
            const int kb = kq & 1;
            #pragma unroll
            for (int mt = 0; mt < 4; mt++) {
                if (mt < 3) {
                    ldsm4(af[(mt + 1) & 1],
                          aBase + (mt + 1) * (16 * ROWP2) + kq * 32);
                } else if (kq < 3) {
                    ldsm4(bq[kb ^ 1],     bBase + (kq + 1) * 32);
                    ldsm4(bq[kb ^ 1] + 4, bBase + 16 * ROWP2 + (kq + 1) * 32);
                    ldsm4(af[0],          aBase + (kq + 1) * 32);
                }
                const uint32_t* B = bq[kb];
                const uint32_t* A = af[mt & 1];
                mma_fp16(acc[mt][0], A, B[0], B[2]);
                mma_fp16(acc[mt][1], A, B[1], B[3]);
                mma_fp16(acc[mt][2], A, B[4], B[6]);
                mma_fp16(acc[mt][3], A, B[5], B[7]);
            }
        }
    }

    // epilogue: RK4 bookkeeping
    const float dt = ts[step + 1] - ts[step];
    const float cn = cnext * dt;
    const float s6 = dt * (1.0f / 6.0f);

    #pragma unroll
    for (int mt = 0; mt < 4; mt++) {
        #pragma unroll
        for (int h = 0; h < 2; h++) {
            int row = m0 + wm * 64 + mt * 16 + r + 8 * h;   // = b*NTRAJ + n
            #pragma unroll
            for (int nt = 0; nt < 4; nt++) {
                int col = n0 + wn * 32 + nt * 8 + 2 * cq;
                float v0 = acc[mt][nt][2 * h + 0];
                float v1 = acc[mt][nt][2 * h + 1];
                size_t idx = (size_t)row * LAT + col;
                if (mode == 0) {
                    g_ksum[idx] = v0;  g_ksum[idx + 1] = v1;
                    float xi0 = fmaf(cn, v0, g_x[idx]);
                    float xi1 = fmaf(cn, v1, g_x[idx + 1]);
                    *(uint32_t*)((char*)g_xin + idx * 2) = pack_h2(xi0, xi1);
                } else if (mode == 1) {
                    g_ksum[idx]     += 2.f * v0;
                    g_ksum[idx + 1] += 2.f * v1;
                    float xi0 = fmaf(cn, v0, g_x[idx]);
                    float xi1 = fmaf(cn, v1, g_x[idx + 1]);
                    *(uint32_t*)((char*)g_xin + idx * 2) = pack_h2(xi0, xi1);
                } else {
                    float x0 = g_x[idx] + s6 * (g_ksum[idx] + v0);
                    float x1 = g_x[idx + 1] + s6 * (g_ksum[idx + 1] + v1);
                    g_x[idx] = x0;   g_x[idx + 1] = x1;
                    *(uint32_t*)((char*)g_xin + idx * 2) = pack_h2(x0, x1);
                    size_t o = ((size_t)row * TSTEPS + (step + 1)) * LAT + col;
                    out[o] = x0; out[o + 1] = x1;
                }
            }
        }
    }
}

// ---------------- launch ------------------------------------------------------
extern "C" void kernel_launch(void* const* d_in, const int* in_sizes, int n_in,
                              void* d_out, int out_size) {
    const float* fp = (const float*)d_in[0];
    const float* ts = (const float*)d_in[1];
    const float* W1 = (const float*)d_in[2];
    const float* b1 = (const float*)d_in[3];
    const float* W2 = (const float*)d_in[4];
    float* out = (float*)d_out;

    static int attr_done = 0;
    if (!attr_done) {
        cudaFuncSetAttribute(k_g1, cudaFuncAttributeMaxDynamicSharedMemorySize, SM1);
        cudaFuncSetAttribute(k_g2, cudaFuncAttributeMaxDynamicSharedMemorySize, SM2);
        attr_done = 1;
    }

    k_init<<<(MTOT * LAT + 255) / 256, 256>>>(fp, out);
    k_w1t<<<(LAT * HID + 255) / 256, 256>>>(W1);
    k_w2t<<<(HID * LAT + 255) / 256, 256>>>(W2);

    dim3 g1(HID / 128, MTOT / 128);   // (8, 128) = 1024 blocks
    dim3 g2(LAT / 128, MTOT / 128);   // (2, 128) = 256 blocks

    for (int s = 0; s < TSTEPS - 1; s++) {
        // eval 1 -> k1: ksum = k1,  xin = x + 0.5*dt*k1
        k_g1<<<g1, 256, SM1>>>(b1);
        k_g2<<<g2, 256, SM2>>>(ts, s, 0, 0.5f, out);
        // eval 2 -> k2: ksum += 2*k2, xin = x + 0.5*dt*k2
        k_g1<<<g1, 256, SM1>>>(b1);
        k_g2<<<g2, 256, SM2>>>(ts, s, 1, 0.5f, out);
        // eval 3 -> k3: ksum += 2*k3, xin = x + dt*k3
        k_g1<<<g1, 256, SM1>>>(b1);
        k_g2<<<g2, 256, SM2>>>(ts, s, 1, 1.0f, out);
        // eval 4 -> k4: x += dt/6*(ksum + k4); write slice; xin = x_new
        k_g1<<<g1, 256, SM1>>>(b1);
        k_g2<<<g2, 256, SM2>>>(ts, s, 2, 0.0f, out);
    }
}